// round 1
// baseline (speedup 1.0000x reference)
#include <cuda_runtime.h>
#include <cuda_bf16.h>
#include <cstdint>

// ---------------------------------------------------------------------------
// SelfAttentionDtwBias: B=8,H=8,S=1024,D=64,C=21
// out = [output (B*H*S*D) | attention (B*H*S*S)] fp32
// ---------------------------------------------------------------------------

typedef unsigned long long ull;

#define B_ 8
#define H_ 8
#define S_ 1024
#define D_ 64
#define C_ 21

// scratch (device globals: allocation-free per harness rules)
__device__ float g_bias[(size_t)B_ * H_ * S_ * S_]; // 268 MB: per-head bias+mask
__device__ float g_KT[(size_t)B_ * H_ * D_ * S_];   // 16 MB: K transposed [bh][d][k]

__device__ __forceinline__ ull pk2(float lo, float hi) {
    ull r; asm("mov.b64 %0, {%1, %2};" : "=l"(r) : "f"(lo), "f"(hi)); return r;
}
__device__ __forceinline__ float2 upk2(ull v) {
    float2 r; asm("mov.b64 {%0, %1}, %2;" : "=f"(r.x), "=f"(r.y) : "l"(v)); return r;
}
__device__ __forceinline__ ull fma2(ull a, ull b, ull c) {
    ull d; asm("fma.rn.f32x2 %0, %1, %2, %3;" : "=l"(d) : "l"(a), "l"(b), "l"(c)); return d;
}

// ---------------------------------------------------------------------------
// Kernel 0: transpose K[bh][k][d] -> g_KT[bh][d][k]
// ---------------------------------------------------------------------------
__global__ void transpose_k_kernel(const float* __restrict__ K, float* __restrict__ KT) {
    __shared__ float ts[32][33];
    const int k0 = blockIdx.x * 32;
    const int d0 = blockIdx.y * 32;
    const int bh = blockIdx.z;
    const int tx = threadIdx.x, ty = threadIdx.y;
    const float* src = K + (size_t)bh * S_ * D_;
#pragma unroll
    for (int i = 0; i < 4; i++) {
        int kk = ty + i * 8;
        ts[kk][tx] = src[(size_t)(k0 + kk) * D_ + d0 + tx];
    }
    __syncthreads();
    float* dst = KT + (size_t)bh * D_ * S_;
#pragma unroll
    for (int i = 0; i < 4; i++) {
        int dd = ty + i * 8;
        dst[(size_t)(d0 + dd) * S_ + k0 + tx] = ts[tx][dd];
    }
}

// ---------------------------------------------------------------------------
// Kernel 1: g_bias[b,h,q,k] = mask ? (sum_c dtw[b,c,q,k]*W[h,c] + b[h]) : -1e9
// grid (1024, B), 256 threads, 4 qk per thread (float4)
// ---------------------------------------------------------------------------
__global__ void __launch_bounds__(256) bias_mask_kernel(
    const float* __restrict__ dtw, const int* __restrict__ mask,
    const float* __restrict__ W, const float* __restrict__ bv,
    float* __restrict__ biasOut)
{
    __shared__ ull Wd[C_ * H_];   // [c][h], value duplicated in both f32x2 halves
    __shared__ float bsh[H_];
    const int tid = threadIdx.x;
    if (tid < C_ * H_) {
        float w = W[tid];             // W[h][c] row-major
        int h = tid / C_, c = tid % C_;
        Wd[c * H_ + h] = pk2(w, w);
    }
    if (tid < H_) bsh[tid] = bv[tid];
    __syncthreads();

    const size_t b = blockIdx.y;
    const size_t qk = ((size_t)blockIdx.x * 256 + tid) * 4;

    ull acc[H_][2];
#pragma unroll
    for (int h = 0; h < H_; h++) { acc[h][0] = 0ull; acc[h][1] = 0ull; }

#pragma unroll
    for (int c = 0; c < C_; c++) {
        float4 dv = __ldg((const float4*)(dtw + ((b * C_ + c) << 20) + qk));
        ull d0 = pk2(dv.x, dv.y), d1 = pk2(dv.z, dv.w);
#pragma unroll
        for (int h = 0; h < H_; h++) {
            ull w2 = Wd[c * H_ + h];
            acc[h][0] = fma2(d0, w2, acc[h][0]);
            acc[h][1] = fma2(d1, w2, acc[h][1]);
        }
    }

    int4 mv = __ldg((const int4*)(mask + (b << 20) + qk));
#pragma unroll
    for (int h = 0; h < H_; h++) {
        float2 p0 = upk2(acc[h][0]), p1 = upk2(acc[h][1]);
        float bh = bsh[h];
        float4 o;
        o.x = mv.x ? (p0.x + bh) : -1e9f;
        o.y = mv.y ? (p0.y + bh) : -1e9f;
        o.z = mv.z ? (p1.x + bh) : -1e9f;
        o.w = mv.w ? (p1.y + bh) : -1e9f;
        *(float4*)(biasOut + (((b * H_ + h) << 20) + qk)) = o;
    }
}

// ---------------------------------------------------------------------------
// Kernel 2: fused attention per (b,h, 32-row q-tile).
// smem: scores 32x1032 (132KB) | K-tile transposed 64x256 (64KB, reused as V
// tile 256x64) | Q duplicated-transposed 64x64 (16KB).  256 threads.
// QK: 8q x 4k microtile in f32x2 (a pre-duplicated in smem -> zero-cost dup).
// AV: 2q x 4d microtile in f32x2.
// ---------------------------------------------------------------------------
#define SSC_STRIDE 1032
#define SMEM_FLOATS (32 * SSC_STRIDE + 64 * 256 + 64 * 64)

__global__ void __launch_bounds__(256, 1) attn_fused_kernel(
    const float* __restrict__ Q, const float* __restrict__ V,
    const float* __restrict__ biasg, const float* __restrict__ KTg,
    float* __restrict__ outO, float* __restrict__ outA)
{
    extern __shared__ float sm[];
    float* Ssc = sm;                        // 32 x 1032
    float* Kt  = sm + 32 * SSC_STRIDE;      // 64 x 256 (then V tile 256 x 64)
    float* Qsd = Kt + 64 * 256;             // 64 x 64 (q duplicated pairs)

    const int tid = threadIdx.x;
    const int bh = blockIdx.z * H_ + blockIdx.y;
    const int q0 = blockIdx.x * 32;

    // --- load Q tile, store transposed with each q duplicated (for f32x2 a) ---
    const float* qptr = Q + ((size_t)bh * S_ + q0) * D_;
#pragma unroll
    for (int i = 0; i < 8; i++) {
        int idx = tid + i * 256;
        int q = idx >> 6, d = idx & 63;
        float v = __ldg(qptr + idx);
        Qsd[d * 64 + 2 * q]     = v;
        Qsd[d * 64 + 2 * q + 1] = v;
    }

    // --- QK^T: 4 k-tiles of 256 ---
    const int tk = tid & 63, tq = tid >> 6;   // tk: 64 k-groups of 4, tq: 4 q-groups of 8
    for (int kt = 0; kt < 4; kt++) {
        __syncthreads();
        const float* ksrc = KTg + (size_t)bh * (D_ * S_) + kt * 256;
#pragma unroll
        for (int i = 0; i < 16; i++) {
            int idx = tid + i * 256;
            int d = idx >> 6, kv = idx & 63;
            float4 v = *(const float4*)(ksrc + (size_t)d * S_ + kv * 4);
            *(float4*)&Kt[d * 256 + kv * 4] = v;
        }
        __syncthreads();

        ull acc[8][2];
#pragma unroll
        for (int qi = 0; qi < 8; qi++) { acc[qi][0] = 0ull; acc[qi][1] = 0ull; }

        const float* ka = &Kt[4 * tk];
        const float* qa = &Qsd[16 * tq];
#pragma unroll 8
        for (int d = 0; d < 64; d++) {
            ull b0 = *(const ull*)(ka + d * 256);
            ull b1 = *(const ull*)(ka + d * 256 + 2);
            float4 a01 = *(const float4*)(qa + d * 64);
            float4 a23 = *(const float4*)(qa + d * 64 + 4);
            float4 a45 = *(const float4*)(qa + d * 64 + 8);
            float4 a67 = *(const float4*)(qa + d * 64 + 12);
            ull A[8];
            A[0] = pk2(a01.x, a01.y); A[1] = pk2(a01.z, a01.w);
            A[2] = pk2(a23.x, a23.y); A[3] = pk2(a23.z, a23.w);
            A[4] = pk2(a45.x, a45.y); A[5] = pk2(a45.z, a45.w);
            A[6] = pk2(a67.x, a67.y); A[7] = pk2(a67.z, a67.w);
#pragma unroll
            for (int qi = 0; qi < 8; qi++) {
                acc[qi][0] = fma2(A[qi], b0, acc[qi][0]);
                acc[qi][1] = fma2(A[qi], b1, acc[qi][1]);
            }
        }

        // epilogue: scale + bias (mask already folded), store to score smem
#pragma unroll
        for (int qi = 0; qi < 8; qi++) {
            int r = 8 * tq + qi;
            float4 bb = __ldg((const float4*)(biasg + ((size_t)bh << 20) +
                              (size_t)(q0 + r) * S_ + kt * 256 + 4 * tk));
            float2 p0 = upk2(acc[qi][0]), p1 = upk2(acc[qi][1]);
            float4 o = make_float4(fmaf(p0.x, 0.125f, bb.x), fmaf(p0.y, 0.125f, bb.y),
                                   fmaf(p1.x, 0.125f, bb.z), fmaf(p1.y, 0.125f, bb.w));
            *(float4*)&Ssc[r * SSC_STRIDE + kt * 256 + 4 * tk] = o;
        }
    }
    __syncthreads();

    // --- softmax (rows in smem) + write attention to gmem ---
    {
        const int lane = tid & 31, w = tid >> 5;
#pragma unroll
        for (int rr = 0; rr < 4; rr++) {
            int r = 4 * w + rr;
            float* row = &Ssc[r * SSC_STRIDE];
            float v[32];
            float m = -3.4e38f;
#pragma unroll
            for (int j = 0; j < 32; j++) { v[j] = row[lane + 32 * j]; m = fmaxf(m, v[j]); }
#pragma unroll
            for (int o = 16; o > 0; o >>= 1) m = fmaxf(m, __shfl_xor_sync(0xffffffffu, m, o));
            float s = 0.f;
#pragma unroll
            for (int j = 0; j < 32; j++) { float e = __expf(v[j] - m); v[j] = e; s += e; }
#pragma unroll
            for (int o = 16; o > 0; o >>= 1) s += __shfl_xor_sync(0xffffffffu, s, o);
            float inv = 1.0f / s;
            float* arow = outA + ((size_t)(bh * S_ + q0 + r) << 10);
#pragma unroll
            for (int j = 0; j < 32; j++) {
                float p = v[j] * inv;
                row[lane + 32 * j] = p;
                arow[lane + 32 * j] = p;
            }
        }
    }

    // --- A @ V: accumulate over 4 k-tiles of 256, V tile reuses Kt smem ---
    const int td = tid & 15, tq2 = tid >> 4;  // 16 d-groups of 4, 16 q-groups of 2
    ull o00 = 0ull, o01 = 0ull, o10 = 0ull, o11 = 0ull;
    float* Vt = Kt;
    for (int kt2 = 0; kt2 < 4; kt2++) {
        __syncthreads();
        const float* vsrc = V + ((size_t)bh * S_ + kt2 * 256) * D_;
#pragma unroll
        for (int i = 0; i < 16; i++) {
            int idx = tid + i * 256;
            int k = idx >> 4, dv = idx & 15;
            float4 v = *(const float4*)(vsrc + (size_t)k * D_ + dv * 4);
            *(float4*)&Vt[k * 64 + dv * 4] = v;
        }
        __syncthreads();
        const float* s0 = &Ssc[(2 * tq2) * SSC_STRIDE + kt2 * 256];
        const float* s1 = s0 + SSC_STRIDE;
        const float* vb = &Vt[4 * td];
#pragma unroll 4
        for (int k = 0; k < 256; k++) {
            float a0 = s0[k], a1 = s1[k];
            ull A0 = pk2(a0, a0), A1 = pk2(a1, a1);
            ull b0 = *(const ull*)(vb + k * 64);
            ull b1 = *(const ull*)(vb + k * 64 + 2);
            o00 = fma2(A0, b0, o00); o01 = fma2(A0, b1, o01);
            o10 = fma2(A1, b0, o10); o11 = fma2(A1, b1, o11);
        }
    }
    {
        float2 x0 = upk2(o00), x1 = upk2(o01), y0 = upk2(o10), y1 = upk2(o11);
        size_t base = ((size_t)bh * S_ + q0 + 2 * tq2) * D_ + 4 * td;
        *(float4*)(outO + base)      = make_float4(x0.x, x0.y, x1.x, x1.y);
        *(float4*)(outO + base + D_) = make_float4(y0.x, y0.y, y1.x, y1.y);
    }
}

// ---------------------------------------------------------------------------
extern "C" void kernel_launch(void* const* d_in, const int* in_sizes, int n_in,
                              void* d_out, int out_size) {
    const float* Q   = (const float*)d_in[0];
    const float* K   = (const float*)d_in[1];
    const float* V   = (const float*)d_in[2];
    const float* dtw = (const float*)d_in[3];
    const int*   msk = (const int*)d_in[4];
    const float* W   = (const float*)d_in[5];
    const float* bv  = (const float*)d_in[6];

    float* out  = (float*)d_out;
    float* attn = out + (size_t)B_ * H_ * S_ * D_;

    float *biasg = nullptr, *ktg = nullptr;
    cudaGetSymbolAddress((void**)&biasg, g_bias);
    cudaGetSymbolAddress((void**)&ktg, g_KT);

    cudaFuncSetAttribute(attn_fused_kernel,
                         cudaFuncAttributeMaxDynamicSharedMemorySize,
                         SMEM_FLOATS * (int)sizeof(float));

    transpose_k_kernel<<<dim3(S_ / 32, D_ / 32, B_ * H_), dim3(32, 8)>>>(K, ktg);
    bias_mask_kernel<<<dim3(S_ * S_ / (256 * 4), B_), 256>>>(dtw, msk, W, bv, biasg);
    attn_fused_kernel<<<dim3(S_ / 32, H_, B_), 256, SMEM_FLOATS * (int)sizeof(float)>>>(
        Q, V, biasg, ktg, out, attn);
}

// round 2
// speedup vs baseline: 1.1381x; 1.1381x over previous
#include <cuda_runtime.h>
#include <cuda_bf16.h>
#include <cstdint>

// ---------------------------------------------------------------------------
// SelfAttentionDtwBias: B=8,H=8,S=1024,D=64,C=21
// out = [output (B*H*S*D) | attention (B*H*S*S)] fp32
// R2: f32x2 vectorized over CONTRACTION dim; AV split into own FMA-bound kernel
// ---------------------------------------------------------------------------

typedef unsigned long long ull;

#define B_ 8
#define H_ 8
#define S_ 1024
#define D_ 64
#define C_ 21

__device__ float g_bias[(size_t)B_ * H_ * S_ * S_]; // 268 MB bias+mask folded
__device__ float g_VT[(size_t)B_ * H_ * D_ * S_];   // 16 MB: V transposed [bh][d][k]

__device__ __forceinline__ ull pk2(float lo, float hi) {
    ull r; asm("mov.b64 %0, {%1, %2};" : "=l"(r) : "f"(lo), "f"(hi)); return r;
}
__device__ __forceinline__ float2 upk2(ull v) {
    float2 r; asm("mov.b64 {%0, %1}, %2;" : "=f"(r.x), "=f"(r.y) : "l"(v)); return r;
}
__device__ __forceinline__ ull fma2(ull a, ull b, ull c) {
    ull d; asm("fma.rn.f32x2 %0, %1, %2, %3;" : "=l"(d) : "l"(a), "l"(b), "l"(c)); return d;
}

// ---------------------------------------------------------------------------
// Kernel 0: transpose V[bh][k][d] -> g_VT[bh][d][k]
// ---------------------------------------------------------------------------
__global__ void transpose_v_kernel(const float* __restrict__ V, float* __restrict__ VT) {
    __shared__ float ts[32][33];
    const int k0 = blockIdx.x * 32;
    const int d0 = blockIdx.y * 32;
    const int bh = blockIdx.z;
    const int tx = threadIdx.x, ty = threadIdx.y;
    const float* src = V + (size_t)bh * S_ * D_;
#pragma unroll
    for (int i = 0; i < 4; i++) {
        int kk = ty + i * 8;
        ts[kk][tx] = src[(size_t)(k0 + kk) * D_ + d0 + tx];
    }
    __syncthreads();
    float* dst = VT + (size_t)bh * D_ * S_;
#pragma unroll
    for (int i = 0; i < 4; i++) {
        int dd = ty + i * 8;
        dst[(size_t)(d0 + dd) * S_ + k0 + tx] = ts[tx][dd];
    }
}

// ---------------------------------------------------------------------------
// Kernel 1: g_bias[b,h,q,k] = mask ? (sum_c dtw[b,c,q,k]*W[h,c] + b[h]) : -1e9
// ---------------------------------------------------------------------------
__global__ void __launch_bounds__(256) bias_mask_kernel(
    const float* __restrict__ dtw, const int* __restrict__ mask,
    const float* __restrict__ W, const float* __restrict__ bv,
    float* __restrict__ biasOut)
{
    __shared__ ull Wd[C_ * H_];
    __shared__ float bsh[H_];
    const int tid = threadIdx.x;
    if (tid < C_ * H_) {
        float w = W[tid];             // W[h][c] row-major
        int h = tid / C_, c = tid % C_;
        Wd[c * H_ + h] = pk2(w, w);
    }
    if (tid < H_) bsh[tid] = bv[tid];
    __syncthreads();

    const size_t b = blockIdx.y;
    const size_t qk = ((size_t)blockIdx.x * 256 + tid) * 4;

    ull acc[H_][2];
#pragma unroll
    for (int h = 0; h < H_; h++) { acc[h][0] = 0ull; acc[h][1] = 0ull; }

#pragma unroll
    for (int c = 0; c < C_; c++) {
        float4 dv = __ldg((const float4*)(dtw + ((b * C_ + c) << 20) + qk));
        ull d0 = pk2(dv.x, dv.y), d1 = pk2(dv.z, dv.w);
#pragma unroll
        for (int h = 0; h < H_; h++) {
            ull w2 = Wd[c * H_ + h];
            acc[h][0] = fma2(d0, w2, acc[h][0]);
            acc[h][1] = fma2(d1, w2, acc[h][1]);
        }
    }

    int4 mv = __ldg((const int4*)(mask + (b << 20) + qk));
#pragma unroll
    for (int h = 0; h < H_; h++) {
        float2 p0 = upk2(acc[h][0]), p1 = upk2(acc[h][1]);
        float bh = bsh[h];
        float4 o;
        o.x = mv.x ? (p0.x + bh) : -1e9f;
        o.y = mv.y ? (p0.y + bh) : -1e9f;
        o.z = mv.z ? (p1.x + bh) : -1e9f;
        o.w = mv.w ? (p1.y + bh) : -1e9f;
        *(float4*)(biasOut + (((b * H_ + h) << 20) + qk)) = o;
    }
}

// ---------------------------------------------------------------------------
// Kernel 2: QK^T + bias + softmax, writes attention. f32x2 over d (contraction).
// Block = (32 q rows, one bh). 256 thr: qg=tid>>6 (warp-uniform), kg=tid&63.
// Per thread 8q x 4k, k strided {kg, kg+64, kg+128, kg+192}.
// ---------------------------------------------------------------------------
#define SST 1032
#define KST 68
#define QST 68
#define QK_SMEM (32 * SST + 256 * KST + 32 * QST)

__global__ void __launch_bounds__(256, 1) qk_softmax_kernel(
    const float* __restrict__ Q, const float* __restrict__ K,
    const float* __restrict__ biasg, float* __restrict__ outA)
{
    extern __shared__ float sm[];
    float* Ssc = sm;                    // 32 x 1032
    float* Ks  = sm + 32 * SST;         // 256 x 68
    float* Qs  = Ks + 256 * KST;        // 32 x 68

    const int tid = threadIdx.x;
    const int bh = blockIdx.z * H_ + blockIdx.y;
    const int q0 = blockIdx.x * 32;

    // load Q tile (plain, d-contiguous)
    const float* qptr = Q + ((size_t)bh * S_ + q0) * D_;
#pragma unroll
    for (int i = 0; i < 8; i++) {
        int idx = tid + i * 256;
        Qs[(idx >> 6) * QST + (idx & 63)] = __ldg(qptr + idx);
    }

    const int qg = tid >> 6;   // warp-uniform
    const int kg = tid & 63;
    const float* bbase = biasg + ((size_t)bh << 20) + (size_t)(q0 + 8 * qg) * S_;

    for (int kt = 0; kt < 4; kt++) {
        __syncthreads();
        const float* kptr = K + ((size_t)bh * S_ + kt * 256) * D_;
#pragma unroll
        for (int i = 0; i < 16; i++) {
            int idx = tid + i * 256;
            int k = idx >> 4, c = idx & 15;
            float4 v = __ldg((const float4*)(kptr + (size_t)k * D_ + 4 * c));
            *(float4*)&Ks[k * KST + 4 * c] = v;
        }
        __syncthreads();

        ull acc[8][4];
#pragma unroll
        for (int qi = 0; qi < 8; qi++)
#pragma unroll
            for (int j = 0; j < 4; j++) acc[qi][j] = 0ull;

#pragma unroll 4
        for (int d = 0; d < 64; d += 4) {
            ull bp0[4], bp1[4];
#pragma unroll
            for (int j = 0; j < 4; j++) {
                float4 bb = *(const float4*)&Ks[(kg + 64 * j) * KST + d];
                bp0[j] = pk2(bb.x, bb.y);
                bp1[j] = pk2(bb.z, bb.w);
            }
#pragma unroll
            for (int qi = 0; qi < 8; qi++) {
                float4 a = *(const float4*)&Qs[(8 * qg + qi) * QST + d];
                ull a0 = pk2(a.x, a.y), a1 = pk2(a.z, a.w);
#pragma unroll
                for (int j = 0; j < 4; j++) {
                    acc[qi][j] = fma2(a0, bp0[j], acc[qi][j]);
                    acc[qi][j] = fma2(a1, bp1[j], acc[qi][j]);
                }
            }
        }

        // epilogue: horizontal add + scale + bias(mask folded)
#pragma unroll
        for (int qi = 0; qi < 8; qi++) {
            const float* brow = bbase + (size_t)qi * S_ + kt * 256 + kg;
            float* srow = &Ssc[(8 * qg + qi) * SST + kt * 256 + kg];
#pragma unroll
            for (int j = 0; j < 4; j++) {
                float2 p = upk2(acc[qi][j]);
                srow[64 * j] = fmaf(p.x + p.y, 0.125f, __ldg(brow + 64 * j));
            }
        }
    }
    __syncthreads();

    // softmax rows in smem, write attention
    {
        const int lane = tid & 31, w = tid >> 5;
#pragma unroll
        for (int rr = 0; rr < 4; rr++) {
            int r = 4 * w + rr;
            float* row = &Ssc[r * SST];
            float v[32];
            float m = -3.4e38f;
#pragma unroll
            for (int j = 0; j < 32; j++) { v[j] = row[lane + 32 * j]; m = fmaxf(m, v[j]); }
#pragma unroll
            for (int o = 16; o > 0; o >>= 1) m = fmaxf(m, __shfl_xor_sync(0xffffffffu, m, o));
            float s = 0.f;
#pragma unroll
            for (int j = 0; j < 32; j++) { float e = __expf(v[j] - m); v[j] = e; s += e; }
#pragma unroll
            for (int o = 16; o > 0; o >>= 1) s += __shfl_xor_sync(0xffffffffu, s, o);
            float inv = 1.0f / s;
            float* arow = outA + ((size_t)(bh * S_ + q0 + r) << 10);
#pragma unroll
            for (int j = 0; j < 32; j++) {
                arow[lane + 32 * j] = v[j] * inv;
            }
        }
    }
}

// ---------------------------------------------------------------------------
// Kernel 3: O = A @ V. f32x2 over k (contraction). A read back from gmem
// (k-contiguous), V pre-transposed in g_VT (k-contiguous rows).
// Block = (32 q, one bh), 256 thr: warp -> (qg=w>>1, split=w&1) uniform;
// lane dg owns d = {dg, dg+32}. k-split 2 halves, smem reduction at end.
// ---------------------------------------------------------------------------
#define AST 260
#define VST 260
#define AV_SMEM (32 * AST + 64 * VST)

__global__ void __launch_bounds__(256, 2) av_kernel(
    const float* __restrict__ A, const float* __restrict__ VT,
    float* __restrict__ outO)
{
    extern __shared__ float sm[];
    float* As = sm;                 // 32 x 260 (k-chunk 256)
    float* Vs = sm + 32 * AST;      // 64 x 260

    const int tid = threadIdx.x;
    const int bh = blockIdx.y;
    const int q0 = blockIdx.x * 32;
    const int w = tid >> 5;
    const int qg = w >> 1;          // warp-uniform, 0..3
    const int split = w & 1;        // warp-uniform
    const int dg = tid & 31;

    ull acc[8][2];
#pragma unroll
    for (int qi = 0; qi < 8; qi++) { acc[qi][0] = 0ull; acc[qi][1] = 0ull; }

    const float* aptr = A + ((size_t)(bh * S_ + q0) << 10);
    const float* vptr = VT + (size_t)bh * D_ * S_;

    for (int kc = 0; kc < 1024; kc += 256) {
        __syncthreads();
#pragma unroll
        for (int i = 0; i < 8; i++) {
            int idx = tid + i * 256;
            int q = idx >> 6, c = idx & 63;
            float4 v = __ldg((const float4*)(aptr + ((size_t)q << 10) + kc + 4 * c));
            *(float4*)&As[q * AST + 4 * c] = v;
        }
#pragma unroll
        for (int i = 0; i < 16; i++) {
            int idx = tid + i * 256;
            int d = idx >> 6, c = idx & 63;
            float4 v = __ldg((const float4*)(vptr + ((size_t)d << 10) + kc + 4 * c));
            *(float4*)&Vs[d * VST + 4 * c] = v;
        }
        __syncthreads();

        const int kbase = split * 128;
#pragma unroll 4
        for (int kk = 0; kk < 128; kk += 4) {
            int k = kbase + kk;
            float4 b0 = *(const float4*)&Vs[dg * VST + k];
            float4 b1 = *(const float4*)&Vs[(dg + 32) * VST + k];
            ull b00 = pk2(b0.x, b0.y), b01 = pk2(b0.z, b0.w);
            ull b10 = pk2(b1.x, b1.y), b11 = pk2(b1.z, b1.w);
#pragma unroll
            for (int qi = 0; qi < 8; qi++) {
                float4 a = *(const float4*)&As[(8 * qg + qi) * AST + k];
                ull a0 = pk2(a.x, a.y), a1 = pk2(a.z, a.w);
                acc[qi][0] = fma2(a0, b00, acc[qi][0]);
                acc[qi][0] = fma2(a1, b01, acc[qi][0]);
                acc[qi][1] = fma2(a0, b10, acc[qi][1]);
                acc[qi][1] = fma2(a1, b11, acc[qi][1]);
            }
        }
    }

    // horizontal add
    float o[8][2];
#pragma unroll
    for (int qi = 0; qi < 8; qi++) {
#pragma unroll
        for (int e = 0; e < 2; e++) {
            float2 p = upk2(acc[qi][e]);
            o[qi][e] = p.x + p.y;
        }
    }

    // reduce the two k-splits via smem (reuse As)
    __syncthreads();
    if (split == 1) {
#pragma unroll
        for (int qi = 0; qi < 8; qi++) {
            As[(8 * qg + qi) * 64 + 32 * 0 + dg] = o[qi][0];
            As[(8 * qg + qi) * 64 + 32 * 1 + dg] = o[qi][1];
        }
    }
    __syncthreads();
    if (split == 0) {
        float* obase = outO + ((size_t)(bh * S_ + q0 + 8 * qg)) * D_;
#pragma unroll
        for (int qi = 0; qi < 8; qi++) {
#pragma unroll
            for (int e = 0; e < 2; e++) {
                float v = o[qi][e] + As[(8 * qg + qi) * 64 + 32 * e + dg];
                obase[(size_t)qi * D_ + 32 * e + dg] = v;
            }
        }
    }
}

// ---------------------------------------------------------------------------
extern "C" void kernel_launch(void* const* d_in, const int* in_sizes, int n_in,
                              void* d_out, int out_size) {
    const float* Q   = (const float*)d_in[0];
    const float* K   = (const float*)d_in[1];
    const float* V   = (const float*)d_in[2];
    const float* dtw = (const float*)d_in[3];
    const int*   msk = (const int*)d_in[4];
    const float* W   = (const float*)d_in[5];
    const float* bv  = (const float*)d_in[6];

    float* out  = (float*)d_out;
    float* attn = out + (size_t)B_ * H_ * S_ * D_;

    float *biasg = nullptr, *vtg = nullptr;
    cudaGetSymbolAddress((void**)&biasg, g_bias);
    cudaGetSymbolAddress((void**)&vtg, g_VT);

    cudaFuncSetAttribute(qk_softmax_kernel,
                         cudaFuncAttributeMaxDynamicSharedMemorySize,
                         QK_SMEM * (int)sizeof(float));
    cudaFuncSetAttribute(av_kernel,
                         cudaFuncAttributeMaxDynamicSharedMemorySize,
                         AV_SMEM * (int)sizeof(float));

    transpose_v_kernel<<<dim3(S_ / 32, D_ / 32, B_ * H_), dim3(32, 8)>>>(V, vtg);
    bias_mask_kernel<<<dim3(S_ * S_ / (256 * 4), B_), 256>>>(dtw, msk, W, bv, biasg);
    qk_softmax_kernel<<<dim3(S_ / 32, H_, B_), 256, QK_SMEM * (int)sizeof(float)>>>(
        Q, K, biasg, attn);
    av_kernel<<<dim3(S_ / 32, B_ * H_), 256, AV_SMEM * (int)sizeof(float)>>>(
        attn, vtg, out);
}

// round 3
// speedup vs baseline: 1.2200x; 1.0720x over previous
#include <cuda_runtime.h>
#include <cuda_bf16.h>
#include <cstdint>

// ---------------------------------------------------------------------------
// SelfAttentionDtwBias: B=8,H=8,S=1024,D=64,C=21
// out = [output (B*H*S*D) | attention (B*H*S*S)] fp32
// R3: warp tile 16q x 64x, lane tile 8q x 4x (2-way q-split across lanes)
//     -> crossbar phases per FMA2 cycle halved vs R2; AV no k-split.
// ---------------------------------------------------------------------------

typedef unsigned long long ull;

#define B_ 8
#define H_ 8
#define S_ 1024
#define D_ 64
#define C_ 21

__device__ float g_bias[(size_t)B_ * H_ * S_ * S_]; // 268 MB bias+mask folded
__device__ float g_VT[(size_t)B_ * H_ * D_ * S_];   // 16 MB: V^T [bh][d][k]

__device__ __forceinline__ ull pk2(float lo, float hi) {
    ull r; asm("mov.b64 %0, {%1, %2};" : "=l"(r) : "f"(lo), "f"(hi)); return r;
}
__device__ __forceinline__ float2 upk2(ull v) {
    float2 r; asm("mov.b64 {%0, %1}, %2;" : "=f"(r.x), "=f"(r.y) : "l"(v)); return r;
}
__device__ __forceinline__ ull fma2(ull a, ull b, ull c) {
    ull d; asm("fma.rn.f32x2 %0, %1, %2, %3;" : "=l"(d) : "l"(a), "l"(b), "l"(c)); return d;
}

// ---------------------------------------------------------------------------
// Kernel 0: transpose V[bh][k][d] -> g_VT[bh][d][k]
// ---------------------------------------------------------------------------
__global__ void transpose_v_kernel(const float* __restrict__ V, float* __restrict__ VT) {
    __shared__ float ts[32][33];
    const int k0 = blockIdx.x * 32;
    const int d0 = blockIdx.y * 32;
    const int bh = blockIdx.z;
    const int tx = threadIdx.x, ty = threadIdx.y;
    const float* src = V + (size_t)bh * S_ * D_;
#pragma unroll
    for (int i = 0; i < 4; i++) {
        int kk = ty + i * 8;
        ts[kk][tx] = src[(size_t)(k0 + kk) * D_ + d0 + tx];
    }
    __syncthreads();
    float* dst = VT + (size_t)bh * D_ * S_;
#pragma unroll
    for (int i = 0; i < 4; i++) {
        int dd = ty + i * 8;
        dst[(size_t)(d0 + dd) * S_ + k0 + tx] = ts[tx][dd];
    }
}

// ---------------------------------------------------------------------------
// Kernel 1: g_bias[b,h,q,k] = mask ? (sum_c dtw[b,c,q,k]*W[h,c] + b[h]) : -1e9
// ---------------------------------------------------------------------------
__global__ void __launch_bounds__(256) bias_mask_kernel(
    const float* __restrict__ dtw, const int* __restrict__ mask,
    const float* __restrict__ W, const float* __restrict__ bv,
    float* __restrict__ biasOut)
{
    __shared__ ull Wd[C_ * H_];
    __shared__ float bsh[H_];
    const int tid = threadIdx.x;
    if (tid < C_ * H_) {
        float w = W[tid];             // W[h][c] row-major
        int h = tid / C_, c = tid % C_;
        Wd[c * H_ + h] = pk2(w, w);
    }
    if (tid < H_) bsh[tid] = bv[tid];
    __syncthreads();

    const size_t b = blockIdx.y;
    const size_t qk = ((size_t)blockIdx.x * 256 + tid) * 4;

    ull acc[H_][2];
#pragma unroll
    for (int h = 0; h < H_; h++) { acc[h][0] = 0ull; acc[h][1] = 0ull; }

#pragma unroll
    for (int c = 0; c < C_; c++) {
        float4 dv = __ldg((const float4*)(dtw + ((b * C_ + c) << 20) + qk));
        ull d0 = pk2(dv.x, dv.y), d1 = pk2(dv.z, dv.w);
#pragma unroll
        for (int h = 0; h < H_; h++) {
            ull w2 = Wd[c * H_ + h];
            acc[h][0] = fma2(d0, w2, acc[h][0]);
            acc[h][1] = fma2(d1, w2, acc[h][1]);
        }
    }

    int4 mv = __ldg((const int4*)(mask + (b << 20) + qk));
#pragma unroll
    for (int h = 0; h < H_; h++) {
        float2 p0 = upk2(acc[h][0]), p1 = upk2(acc[h][1]);
        float bh = bsh[h];
        float4 o;
        o.x = mv.x ? (p0.x + bh) : -1e9f;
        o.y = mv.y ? (p0.y + bh) : -1e9f;
        o.z = mv.z ? (p1.x + bh) : -1e9f;
        o.w = mv.w ? (p1.y + bh) : -1e9f;
        *(float4*)(biasOut + (((b * H_ + h) << 20) + qk)) = o;
    }
}

// ---------------------------------------------------------------------------
// Kernel 2: QK^T + bias + softmax -> attention.
// Block: 32 q rows x one bh, 256 thr (8 warps). Per 256-k tile:
//   warp w: q half = 16*(w&1), k quarter = 64*(w>>1)  (16q x 64k warp tile)
//   lane l: qh=l>>4 (8q), kg=l&15, k strided by 16 (8q x 4k lane tile)
// f32x2 over d (contraction), operands loaded as ulonglong2 (LDS.128).
// ---------------------------------------------------------------------------
#define SST 1032
#define KST 68
#define QST 68
#define QK_SMEM (32 * SST + 256 * KST + 32 * QST)

__global__ void __launch_bounds__(256, 1) qk_softmax_kernel(
    const float* __restrict__ Q, const float* __restrict__ K,
    const float* __restrict__ biasg, float* __restrict__ outA)
{
    extern __shared__ float sm[];
    float* Ssc = sm;                    // 32 x 1032
    float* Ks  = sm + 32 * SST;         // 256 x 68
    float* Qs  = Ks + 256 * KST;        // 32 x 68

    const int tid = threadIdx.x;
    const int bh = blockIdx.z * H_ + blockIdx.y;
    const int q0 = blockIdx.x * 32;

    // load Q tile (d-contiguous)
    const float* qptr = Q + ((size_t)bh * S_ + q0) * D_;
#pragma unroll
    for (int i = 0; i < 8; i++) {
        int idx = tid + i * 256;
        Qs[(idx >> 6) * QST + (idx & 63)] = __ldg(qptr + idx);
    }

    const int w = tid >> 5, l = tid & 31;
    const int qh = l >> 4, kg = l & 15;
    const int qloc = 16 * (w & 1) + 8 * qh;   // first of this lane's 8 q rows
    const int kq = 64 * (w >> 1);             // warp's k quarter within tile

    for (int kt = 0; kt < 4; kt++) {
        __syncthreads();
        const float* kptr = K + ((size_t)bh * S_ + kt * 256) * D_;
#pragma unroll
        for (int i = 0; i < 16; i++) {
            int idx = tid + i * 256;
            int k = idx >> 4, c = idx & 15;
            float4 v = __ldg((const float4*)(kptr + (size_t)k * D_ + 4 * c));
            *(float4*)&Ks[k * KST + 4 * c] = v;
        }
        __syncthreads();

        ull acc[8][4];
#pragma unroll
        for (int qi = 0; qi < 8; qi++)
#pragma unroll
            for (int j = 0; j < 4; j++) acc[qi][j] = 0ull;

#pragma unroll 4
        for (int d = 0; d < 64; d += 4) {
            ulonglong2 b[4];
#pragma unroll
            for (int j = 0; j < 4; j++)
                b[j] = *(const ulonglong2*)&Ks[(kq + kg + 16 * j) * KST + d];
#pragma unroll
            for (int qi = 0; qi < 8; qi++) {
                ulonglong2 a = *(const ulonglong2*)&Qs[(qloc + qi) * QST + d];
#pragma unroll
                for (int j = 0; j < 4; j++) {
                    acc[qi][j] = fma2(a.x, b[j].x, acc[qi][j]);
                    acc[qi][j] = fma2(a.y, b[j].y, acc[qi][j]);
                }
            }
        }

        // epilogue: horizontal add + scale + bias(mask folded) -> score smem
        const float* bbase = biasg + ((size_t)bh << 20) + (size_t)(q0) * S_;
#pragma unroll
        for (int qi = 0; qi < 8; qi++) {
            int r = qloc + qi;
            int kb = kt * 256 + kq + kg;
#pragma unroll
            for (int j = 0; j < 4; j++) {
                float2 p = upk2(acc[qi][j]);
                float bb = __ldg(bbase + (size_t)r * S_ + kb + 16 * j);
                Ssc[r * SST + kb + 16 * j] = fmaf(p.x + p.y, 0.125f, bb);
            }
        }
    }
    __syncthreads();

    // softmax rows in smem, write attention
    {
        const int lane = tid & 31, wr = tid >> 5;
#pragma unroll
        for (int rr = 0; rr < 4; rr++) {
            int r = 4 * wr + rr;
            float* row = &Ssc[r * SST];
            float v[32];
            float m = -3.4e38f;
#pragma unroll
            for (int j = 0; j < 32; j++) { v[j] = row[lane + 32 * j]; m = fmaxf(m, v[j]); }
#pragma unroll
            for (int o = 16; o > 0; o >>= 1) m = fmaxf(m, __shfl_xor_sync(0xffffffffu, m, o));
            float s = 0.f;
#pragma unroll
            for (int j = 0; j < 32; j++) { float e = __expf(v[j] - m); v[j] = e; s += e; }
#pragma unroll
            for (int o = 16; o > 0; o >>= 1) s += __shfl_xor_sync(0xffffffffu, s, o);
            float inv = 1.0f / s;
            float* arow = outA + ((size_t)(bh * S_ + q0 + r) << 10);
#pragma unroll
            for (int j = 0; j < 32; j++) {
                arow[lane + 32 * j] = v[j] * inv;
            }
        }
    }
}

// ---------------------------------------------------------------------------
// Kernel 3: O = A @ V.  Block: 64 q x one bh, 128 thr (4 warps).
//   warp w: q = q0 + 16w .. +16 (16q x 64d warp tile)
//   lane l: qh=l>>4 (8q), dgrp=l&15, d strided by 16 (8q x 4d lane tile)
// f32x2 over k; A from gmem (k-contiguous), V^T rows (k-contiguous).
// k-chunks of 128 in smem, stride 132 (bank-clean for stride-1-row lanes).
// ---------------------------------------------------------------------------
#define AST 132
#define VST 132
#define AV_SMEM (64 * AST + 64 * VST)

__global__ void __launch_bounds__(128, 3) av_kernel(
    const float* __restrict__ A, const float* __restrict__ VT,
    float* __restrict__ outO)
{
    extern __shared__ float sm[];
    float* As = sm;                 // 64 x 132 (k-chunk 128)
    float* Vs = sm + 64 * AST;      // 64 x 132

    const int tid = threadIdx.x;
    const int bh = blockIdx.y;
    const int q0 = blockIdx.x * 64;
    const int w = tid >> 5, l = tid & 31;
    const int qh = l >> 4, dgrp = l & 15;
    const int qloc = 16 * w + 8 * qh;

    ull acc[8][4];
#pragma unroll
    for (int qi = 0; qi < 8; qi++)
#pragma unroll
        for (int e = 0; e < 4; e++) acc[qi][e] = 0ull;

    const float* aptr = A + ((size_t)(bh * S_ + q0) << 10);
    const float* vptr = VT + (size_t)bh * D_ * S_;

    for (int kc = 0; kc < 1024; kc += 128) {
        __syncthreads();
#pragma unroll
        for (int i = 0; i < 16; i++) {
            int idx = tid + i * 128;
            int r = idx >> 5, c = idx & 31;
            float4 v = __ldg((const float4*)(aptr + ((size_t)r << 10) + kc + 4 * c));
            *(float4*)&As[r * AST + 4 * c] = v;
        }
#pragma unroll
        for (int i = 0; i < 16; i++) {
            int idx = tid + i * 128;
            int d = idx >> 5, c = idx & 31;
            float4 v = __ldg((const float4*)(vptr + ((size_t)d << 10) + kc + 4 * c));
            *(float4*)&Vs[d * VST + 4 * c] = v;
        }
        __syncthreads();

#pragma unroll 4
        for (int k = 0; k < 128; k += 4) {
            ulonglong2 b[4];
#pragma unroll
            for (int e = 0; e < 4; e++)
                b[e] = *(const ulonglong2*)&Vs[(dgrp + 16 * e) * VST + k];
#pragma unroll
            for (int qi = 0; qi < 8; qi++) {
                ulonglong2 a = *(const ulonglong2*)&As[(qloc + qi) * AST + k];
#pragma unroll
                for (int e = 0; e < 4; e++) {
                    acc[qi][e] = fma2(a.x, b[e].x, acc[qi][e]);
                    acc[qi][e] = fma2(a.y, b[e].y, acc[qi][e]);
                }
            }
        }
    }

    // epilogue: horizontal add, scalar stores (lanes 0-15 consecutive d)
    float* obase = outO + ((size_t)(bh * S_ + q0 + qloc)) * D_;
#pragma unroll
    for (int qi = 0; qi < 8; qi++) {
#pragma unroll
        for (int e = 0; e < 4; e++) {
            float2 p = upk2(acc[qi][e]);
            obase[(size_t)qi * D_ + dgrp + 16 * e] = p.x + p.y;
        }
    }
}

// ---------------------------------------------------------------------------
extern "C" void kernel_launch(void* const* d_in, const int* in_sizes, int n_in,
                              void* d_out, int out_size) {
    const float* Q   = (const float*)d_in[0];
    const float* K   = (const float*)d_in[1];
    const float* V   = (const float*)d_in[2];
    const float* dtw = (const float*)d_in[3];
    const int*   msk = (const int*)d_in[4];
    const float* W   = (const float*)d_in[5];
    const float* bv  = (const float*)d_in[6];

    float* out  = (float*)d_out;
    float* attn = out + (size_t)B_ * H_ * S_ * D_;

    float *biasg = nullptr, *vtg = nullptr;
    cudaGetSymbolAddress((void**)&biasg, g_bias);
    cudaGetSymbolAddress((void**)&vtg, g_VT);

    cudaFuncSetAttribute(qk_softmax_kernel,
                         cudaFuncAttributeMaxDynamicSharedMemorySize,
                         QK_SMEM * (int)sizeof(float));
    cudaFuncSetAttribute(av_kernel,
                         cudaFuncAttributeMaxDynamicSharedMemorySize,
                         AV_SMEM * (int)sizeof(float));

    transpose_v_kernel<<<dim3(S_ / 32, D_ / 32, B_ * H_), dim3(32, 8)>>>(V, vtg);
    bias_mask_kernel<<<dim3(S_ * S_ / (256 * 4), B_), 256>>>(dtw, msk, W, bv, biasg);
    qk_softmax_kernel<<<dim3(S_ / 32, H_, B_), 256, QK_SMEM * (int)sizeof(float)>>>(
        Q, K, biasg, attn);
    av_kernel<<<dim3(S_ / 64, B_ * H_), 128, AV_SMEM * (int)sizeof(float)>>>(
        attn, vtg, out);
}